// round 7
// baseline (speedup 1.0000x reference)
#include <cuda_runtime.h>
#include <cuda_fp16.h>

// SpikeCNN fused: one block = one image, all 8 timesteps.
// R7: conv2 inner loop uses packed fma.rn.f32x2 (FFMA2) — 2 MACs per issue slot
//     and per fma-pipe slot. Weights stored duplicated (w,w) in SMEM so the
//     packed multiplicand is a single broadcast LDS.64. Accumulation order is
//     identical to the scalar version (ic -> di -> dj), each f32x2 lane rounds
//     rn like scalar FFMA => bitwise-identical results.

#define TH 1.0f
#define TSTEPS 8
#define NT 224
#define XPITCH 33          // xpadT: col*33 + row (col-major)
#define C1CP 30            // c1s: c*840 + col*30 + row (col-major)
#define P1P 12             // p1h: [ic][rh(36)][k(12)] halves (k 0..10 used)

__device__ __forceinline__ unsigned long long pk2(float lo, float hi) {
    unsigned long long r;
    asm("mov.b64 %0, {%1,%2};" : "=l"(r) : "f"(lo), "f"(hi));
    return r;
}
__device__ __forceinline__ void fma2(unsigned long long& acc,
                                     unsigned long long a, unsigned long long b) {
    asm("fma.rn.f32x2 %0, %1, %2, %0;" : "+l"(acc) : "l"(a), "l"(b));
}
__device__ __forceinline__ float2 upk(unsigned long long v) {
    float2 r;
    asm("mov.b64 {%0,%1}, %2;" : "=f"(r.x), "=f"(r.y) : "l"(v));
    return r;
}

__global__ __launch_bounds__(NT, 4)
void snn_kernel(const float* __restrict__ x,
                const float* __restrict__ w1, const float* __restrict__ b1,
                const float* __restrict__ w2, const float* __restrict__ b2,
                const float* __restrict__ wf, const float* __restrict__ bf,
                float* __restrict__ out, int nb)
{
    __shared__ __align__(16) float  xpadT[32 * XPITCH];   // 1056 f32
    __shared__ __align__(16) float  c1s[3 * 28 * C1CP];   // 2520 f32 (col-major)
    __shared__ __align__(16) __half p1h[3 * 36 * P1P];    // 1296 halves
    __shared__ __align__(16) float2 w2dd[90 * 5];         // [(oc*3+ic)*5+di][dj] dup (w,w)
    __shared__ float s2L[6 * 196];          // oc*196 + j*28 + (row*2+h)
    __shared__ float p2s[294];
    __shared__ float fcsum[10], mem3s[10], acc3s[10];

    const int tid  = threadIdx.x;
    const int warp = tid >> 5;              // 0..6
    const int lane = tid & 31;
    const int b    = blockIdx.x;

    // ---- init ----
    for (int i = tid; i < 32 * XPITCH; i += NT)  xpadT[i] = 0.f;
    for (int i = tid; i < 3 * 36 * P1P; i += NT) p1h[i]   = __float2half(0.f);
    if (tid < 10) { mem3s[tid] = 0.f; acc3s[tid] = 0.f; }
    // w2 flat index i = row*5 + dj with row = (oc*3+ic)*5+di (0..89)
    for (int i = tid; i < 450; i += NT) {
        float w = w2[i];
        w2dd[i] = make_float2(w, w);
    }
    const float* xb = x + (size_t)b * 784;
    __syncthreads();
    for (int i = tid; i < 784; i += NT) {
        int r = i / 28, c = i % 28;
        xpadT[(c + 2) * XPITCH + (r + 2)] = xb[i];
    }
    __syncthreads();

    // ---- conv1 (once): warps 0..5 -> (c = warp%3, colhalf = warp/3), lane = row ----
    if (warp < 6 && lane < 28) {
        int c = warp % 3, colbase = (warp / 3) * 14, row = lane;
        float wr[25];
        #pragma unroll
        for (int k = 0; k < 25; k++) wr[k] = __ldg(&w1[c * 25 + k]);
        float bias = __ldg(&b1[c]);
        float acc[14];
        #pragma unroll
        for (int j = 0; j < 14; j++) acc[j] = bias;
        #pragma unroll
        for (int di = 0; di < 5; di++) {
            float v[18];
            #pragma unroll
            for (int k = 0; k < 18; k++)
                v[k] = xpadT[(colbase + k) * XPITCH + row + di];
            #pragma unroll
            for (int j = 0; j < 14; j++)
                #pragma unroll
                for (int dj = 0; dj < 5; dj++)
                    acc[j] += v[j + dj] * wr[di * 5 + dj];
        }
        #pragma unroll
        for (int j = 0; j < 14; j++)
            c1s[c * 840 + (colbase + j) * C1CP + row] = acc[j];
    }
    __syncthreads();

    // ---- persistent register state ----
    float mr[12];                           // mem1: 3 tasks x 4 cells (all 7 warps)
    #pragma unroll
    for (int i = 0; i < 12; i++) mr[i] = 0.f;
    float m2r[7];                           // mem2: warps 0..5, oc = warp
    #pragma unroll
    for (int j = 0; j < 7; j++) m2r[j] = 0.f;
    const bool bact = (warp < 6 && lane < 28);
    const float b2r = bact ? __ldg(&b2[warp]) : 0.f;

    const int  pi   = lane % 14;            // phase-A pooled row
    const int  dpj  = lane / 14;            // 0/1
    const bool aact = (lane < 28);

    // ---- time loop ----
    for (int t = 0; t < TSTEPS; t++) {
        // A: mem1 += c1, fire, pool -> p1h (duplicated k-layout, fp16 exact)
        if (aact) {
            #pragma unroll
            for (int i = 0; i < 3; i++) {
                int task = warp * 3 + i;                // 0..20
                int c    = task / 7;
                int pp   = task - 7 * c;
                int pj   = 2 * pp + dpj;
                int base = c * 840 + (2 * pj) * C1CP + 2 * pi;
                float2 ca = *reinterpret_cast<const float2*>(&c1s[base]);
                float2 cb = *reinterpret_cast<const float2*>(&c1s[base + C1CP]);
                float m0 = mr[i * 4 + 0] + ca.x;
                float m1 = mr[i * 4 + 1] + ca.y;
                float m2 = mr[i * 4 + 2] + cb.x;
                float m3 = mr[i * 4 + 3] + cb.y;
                float s0 = (m0 >= TH) ? TH : 0.f;
                float s1 = (m1 >= TH) ? TH : 0.f;
                float s2 = (m2 >= TH) ? TH : 0.f;
                float s3 = (m3 >= TH) ? TH : 0.f;
                mr[i * 4 + 0] = m0 - s0;
                mr[i * 4 + 1] = m1 - s1;
                mr[i * 4 + 2] = m2 - s2;
                mr[i * 4 + 3] = m3 - s3;
                __half val = __float2half_rn(0.25f * (s0 + s1 + s2 + s3));
                int cpad = pj + 2;                      // 2..15
                int rb   = c * 432 + (pi + 2) * 2 * P1P;
                if (cpad <= 10) p1h[rb + cpad] = val;             // h=0 row
                if (cpad >= 7)  p1h[rb + P1P + (cpad - 7)] = val; // h=1 row
            }
        }
        __syncthreads();

        // B: conv2 + mem2 fire. warp = oc (0..5); lane = row*2+h; 7 cols/thread
        // Packed f32x2: acc pairs (a0,a1)(a2,a3)(a4,a5), a6 scalar.
        if (bact) {
            const int oc = warp;
            unsigned long long P0 = pk2(b2r, b2r), P1 = P0, P2 = P0;
            float a6 = b2r;
            #pragma unroll
            for (int ic = 0; ic < 3; ic++) {
                #pragma unroll
                for (int di = 0; di < 5; di++) {
                    const __half2* src = reinterpret_cast<const __half2*>(
                        &p1h[ic * 432 + (lane + 2 * di) * P1P]);
                    uint2 ra  = *reinterpret_cast<const uint2*>(src);
                    uint2 rb2 = *reinterpret_cast<const uint2*>(src + 2);
                    uint2 rc  = *reinterpret_cast<const uint2*>(src + 4);
                    float2 f0 = __half22float2(*reinterpret_cast<__half2*>(&ra.x));
                    float2 f1 = __half22float2(*reinterpret_cast<__half2*>(&ra.y));
                    float2 f2 = __half22float2(*reinterpret_cast<__half2*>(&rb2.x));
                    float2 f3 = __half22float2(*reinterpret_cast<__half2*>(&rb2.y));
                    float2 f4 = __half22float2(*reinterpret_cast<__half2*>(&rc.x));
                    float v10 = __low2float(*reinterpret_cast<__half2*>(&rc.y));
                    // sliding pairs pv[k] = (v[k], v[k+1]), k = 0..8
                    unsigned long long pvs[9];
                    pvs[0] = pk2(f0.x, f0.y);
                    pvs[1] = pk2(f0.y, f1.x);
                    pvs[2] = pk2(f1.x, f1.y);
                    pvs[3] = pk2(f1.y, f2.x);
                    pvs[4] = pk2(f2.x, f2.y);
                    pvs[5] = pk2(f2.y, f3.x);
                    pvs[6] = pk2(f3.x, f3.y);
                    pvs[7] = pk2(f3.y, f4.x);
                    pvs[8] = pk2(f4.x, f4.y);
                    float vs[5] = {f3.x, f3.y, f4.x, f4.y, v10};  // v[6+dj]
                    const unsigned long long* wp =
                        reinterpret_cast<const unsigned long long*>(
                            &w2dd[((oc * 3 + ic) * 5) * 5]);
                    #pragma unroll
                    for (int dj = 0; dj < 5; dj++) {
                        // weight row for this di: w2dd[((oc*3+ic)*5+di)*5 + dj]
                        unsigned long long wv = wp[di * 5 + dj];  // broadcast (w,w)
                        fma2(P0, pvs[dj],     wv);
                        fma2(P1, pvs[dj + 2], wv);
                        fma2(P2, pvs[dj + 4], wv);
                        float ws = __uint_as_float((unsigned)(wv & 0xffffffffULL));
                        a6 += vs[dj] * ws;
                    }
                }
            }
            float2 q0 = upk(P0), q1 = upk(P1), q2 = upk(P2);
            float acc[7] = {q0.x, q0.y, q1.x, q1.y, q2.x, q2.y, a6};
            float* dst = &s2L[oc * 196 + lane];
            #pragma unroll
            for (int j = 0; j < 7; j++) {
                float m  = m2r[j] + acc[j];
                float sp = (m >= TH) ? TH : 0.f;
                m2r[j]   = m - sp;
                dst[j * 28] = sp;
            }
        }
        __syncthreads();

        // C: 2x2 avg-pool layer 2 -> p2 (flatten order oc*49 + po*7 + qo)
        for (int idx = tid; idx < 294; idx += NT) {
            int oc = idx / 49, rem = idx - 49 * oc, po = rem / 7, qo = rem - 7 * po;
            float s = 0.f;
            #pragma unroll
            for (int a = 0; a < 2; a++)
                #pragma unroll
                for (int bb = 0; bb < 2; bb++) {
                    int r  = 2 * po + a, cc = 2 * qo + bb;
                    int h  = (cc >= 7) ? 1 : 0;
                    int jj = cc - 7 * h;
                    s += s2L[oc * 196 + jj * 28 + r * 2 + h];
                }
            p2s[idx] = 0.25f * s;
        }
        __syncthreads();

        // D: fc — warp w reduces row w (and 7+w for w<3)
        {
            float part = 0.f;
            const float* wrow = wf + warp * 294;
            for (int k = lane; k < 294; k += 32) part += p2s[k] * __ldg(&wrow[k]);
            #pragma unroll
            for (int s = 16; s > 0; s >>= 1) part += __shfl_xor_sync(0xffffffffu, part, s);
            if (lane == 0) fcsum[warp] = part;
            if (warp < 3) {
                float part2 = 0.f;
                const float* wrow2 = wf + (7 + warp) * 294;
                for (int k = lane; k < 294; k += 32) part2 += p2s[k] * __ldg(&wrow2[k]);
                #pragma unroll
                for (int s = 16; s > 0; s >>= 1) part2 += __shfl_xor_sync(0xffffffffu, part2, s);
                if (lane == 0) fcsum[7 + warp] = part2;
            }
        }
        __syncthreads();

        // E: mem3 update, fire, accumulate, emit running average at t=3,7
        if (tid < 10) {
            float m  = mem3s[tid] + fcsum[tid] + __ldg(&bf[tid]);
            float sp = (m >= TH) ? TH : 0.f;
            mem3s[tid] = m - sp;
            float a = acc3s[tid] + sp;
            acc3s[tid] = a;
            if (t == 3) out[(size_t)b * 10 + tid] = a * 0.25f;
            if (t == 7) out[(size_t)nb * 10 + (size_t)b * 10 + tid] = a * 0.125f;
        }
        __syncthreads();
    }
}

extern "C" void kernel_launch(void* const* d_in, const int* in_sizes, int n_in,
                              void* d_out, int out_size)
{
    const float* x  = (const float*)d_in[0];
    const float* w1 = (const float*)d_in[1];
    const float* b1 = (const float*)d_in[2];
    const float* w2 = (const float*)d_in[3];
    const float* b2 = (const float*)d_in[4];
    const float* wf = (const float*)d_in[5];
    const float* bf = (const float*)d_in[6];
    float* out = (float*)d_out;

    int nb = in_sizes[0] / 784;   // 4096
    snn_kernel<<<nb, NT>>>(x, w1, b1, w2, b2, wf, bf, out, nb);
}

// round 9
// speedup vs baseline: 1.1393x; 1.1393x over previous
#include <cuda_runtime.h>
#include <cuda_fp16.h>

// SpikeCNN fused: one block = one image, all 8 timesteps.
// R9 = R8 + missing prologue barrier (conv1 writes c1s -> phaseA reads c1s).
//   - 2 barriers per timestep (was 5)
//   - s2 stored pool-group-contiguous -> fc pools inline via LDS.128 (phase C gone)
//   - mem3/acc3 in per-warp registers, E fused into D (no fcsum smem)
//   - A(t+1) runs in the same no-barrier region as D (independent dataflow)

#define TH 1.0f
#define TSTEPS 8
#define NT 224
#define XPITCH 33          // xpadT: col*33 + row (col-major)
#define C1CP 30            // c1s: c*840 + col*30 + row (col-major)
#define P1P 12             // p1h: [ic][rh(36)][k(12)] halves (k 0..10 used)

__global__ __launch_bounds__(NT, 4)
void snn_kernel(const float* __restrict__ x,
                const float* __restrict__ w1, const float* __restrict__ b1,
                const float* __restrict__ w2, const float* __restrict__ b2,
                const float* __restrict__ wf, const float* __restrict__ bf,
                float* __restrict__ out, int nb)
{
    __shared__ __align__(16) float  xpadT[32 * XPITCH];   // 1056 f32
    __shared__ __align__(16) float  c1s[3 * 28 * C1CP];   // 2520 f32 (col-major)
    __shared__ __align__(16) __half p1h[3 * 36 * P1P];    // 1296 halves
    __shared__ __align__(16) float  w2d[6 * 3 * 5 * 8];   // [oc][ic][di][8] padded rows
    __shared__ __align__(16) float  s2P[6 * 196];         // [oc][group(49)][sub(4)]

    const int tid  = threadIdx.x;
    const int warp = tid >> 5;              // 0..6
    const int lane = tid & 31;
    const int b    = blockIdx.x;

    // ---- init ----
    for (int i = tid; i < 32 * XPITCH; i += NT)  xpadT[i] = 0.f;
    for (int i = tid; i < 3 * 36 * P1P; i += NT) p1h[i]   = __float2half(0.f);
    for (int i = tid; i < 720; i += NT)          w2d[i]   = 0.f;
    __syncthreads();
    for (int i = tid; i < 450; i += NT) {
        int g = i / 5, dj = i - 5 * g;      // g = (oc*3+ic)*5+di
        w2d[g * 8 + dj] = w2[i];
    }
    const float* xb = x + (size_t)b * 784;
    for (int i = tid; i < 784; i += NT) {
        int r = i / 28, c = i % 28;
        xpadT[(c + 2) * XPITCH + (r + 2)] = xb[i];
    }
    __syncthreads();

    // ---- conv1 (once): warps 0..5 -> (c = warp%3, colhalf = warp/3), lane = row ----
    if (warp < 6 && lane < 28) {
        int c = warp % 3, colbase = (warp / 3) * 14, row = lane;
        float wr[25];
        #pragma unroll
        for (int k = 0; k < 25; k++) wr[k] = __ldg(&w1[c * 25 + k]);
        float bias = __ldg(&b1[c]);
        float acc[14];
        #pragma unroll
        for (int j = 0; j < 14; j++) acc[j] = bias;
        #pragma unroll
        for (int di = 0; di < 5; di++) {
            float v[18];
            #pragma unroll
            for (int k = 0; k < 18; k++)
                v[k] = xpadT[(colbase + k) * XPITCH + row + di];
            #pragma unroll
            for (int j = 0; j < 14; j++)
                #pragma unroll
                for (int dj = 0; dj < 5; dj++)
                    acc[j] += v[j + dj] * wr[di * 5 + dj];
        }
        #pragma unroll
        for (int j = 0; j < 14; j++)
            c1s[c * 840 + (colbase + j) * C1CP + row] = acc[j];
    }
    __syncthreads();   // <-- R9 fix: c1s must be complete before phaseA reads it

    // ---- persistent register state ----
    float mr[12];                           // mem1: 3 tasks x 4 cells (all 7 warps)
    #pragma unroll
    for (int i = 0; i < 12; i++) mr[i] = 0.f;
    float m2r[7];                           // mem2: warps 0..5, oc = warp
    #pragma unroll
    for (int j = 0; j < 7; j++) m2r[j] = 0.f;
    const bool bact = (warp < 6 && lane < 28);
    const float b2r = bact ? __ldg(&b2[warp]) : 0.f;
    // mem3/acc3: warp-uniform registers. Row 'warp' in every warp; rows 7+w in warps 0..2.
    float m3a = 0.f, a3a = 0.f, m3b = 0.f, a3b = 0.f;
    const float bfa = __ldg(&bf[warp]);
    const float bfb = (warp < 3) ? __ldg(&bf[7 + warp]) : 0.f;

    const int  pi   = lane % 14;            // phase-A pooled row
    const int  dpj  = lane / 14;            // 0/1
    const bool aact = (lane < 28);

    // Phase A: mem1 += c1, fire, 2x2 pool -> p1h (duplicated k-layout, fp16 exact)
    auto phaseA = [&]() {
        if (aact) {
            #pragma unroll
            for (int i = 0; i < 3; i++) {
                int task = warp * 3 + i;                // 0..20
                int c    = task / 7;
                int pp   = task - 7 * c;
                int pj   = 2 * pp + dpj;
                int base = c * 840 + (2 * pj) * C1CP + 2 * pi;
                float2 ca = *reinterpret_cast<const float2*>(&c1s[base]);
                float2 cb = *reinterpret_cast<const float2*>(&c1s[base + C1CP]);
                float m0 = mr[i * 4 + 0] + ca.x;
                float m1 = mr[i * 4 + 1] + ca.y;
                float m2 = mr[i * 4 + 2] + cb.x;
                float m3 = mr[i * 4 + 3] + cb.y;
                float s0 = (m0 >= TH) ? TH : 0.f;
                float s1 = (m1 >= TH) ? TH : 0.f;
                float s2 = (m2 >= TH) ? TH : 0.f;
                float s3 = (m3 >= TH) ? TH : 0.f;
                mr[i * 4 + 0] = m0 - s0;
                mr[i * 4 + 1] = m1 - s1;
                mr[i * 4 + 2] = m2 - s2;
                mr[i * 4 + 3] = m3 - s3;
                __half val = __float2half_rn(0.25f * (s0 + s1 + s2 + s3));
                int cpad = pj + 2;                      // 2..15
                int rb   = c * 432 + (pi + 2) * 2 * P1P;
                if (cpad <= 10) p1h[rb + cpad] = val;             // h=0 row
                if (cpad >= 7)  p1h[rb + P1P + (cpad - 7)] = val; // h=1 row
            }
        }
    };

    phaseA();            // produce p1 for t=0
    __syncthreads();

    // ---- time loop: 2 barriers per timestep ----
    for (int t = 0; t < TSTEPS; t++) {
        // B: conv2 + mem2 fire. warp = oc (0..5); lane = row*2+h; 7 cols/thread
        if (bact) {
            const int oc  = warp;
            const int row = lane >> 1, h = lane & 1;
            float acc[7];
            #pragma unroll
            for (int j = 0; j < 7; j++) acc[j] = b2r;
            #pragma unroll
            for (int ic = 0; ic < 3; ic++) {
                #pragma unroll
                for (int di = 0; di < 5; di++) {
                    // v window: 11 halves -> 12 floats (3x LDS.64, conflict-free)
                    const __half2* src = reinterpret_cast<const __half2*>(
                        &p1h[ic * 432 + (lane + 2 * di) * P1P]);
                    uint2 ra  = *reinterpret_cast<const uint2*>(src);
                    uint2 rb2 = *reinterpret_cast<const uint2*>(src + 2);
                    uint2 rc  = *reinterpret_cast<const uint2*>(src + 4);
                    float2 f0 = __half22float2(*reinterpret_cast<__half2*>(&ra.x));
                    float2 f1 = __half22float2(*reinterpret_cast<__half2*>(&ra.y));
                    float2 f2 = __half22float2(*reinterpret_cast<__half2*>(&rb2.x));
                    float2 f3 = __half22float2(*reinterpret_cast<__half2*>(&rb2.y));
                    float2 f4 = __half22float2(*reinterpret_cast<__half2*>(&rc.x));
                    float2 f5 = __half22float2(*reinterpret_cast<__half2*>(&rc.y));
                    float v[12] = {f0.x, f0.y, f1.x, f1.y, f2.x, f2.y,
                                   f3.x, f3.y, f4.x, f4.y, f5.x, f5.y};
                    const float* wp = &w2d[((oc * 3 + ic) * 5 + di) * 8];
                    float4 w4 = *reinterpret_cast<const float4*>(wp);
                    float  w5 = wp[4];
                    float wrow[5] = {w4.x, w4.y, w4.z, w4.w, w5};
                    #pragma unroll
                    for (int j = 0; j < 7; j++)
                        #pragma unroll
                        for (int dj = 0; dj < 5; dj++)
                            acc[j] += v[j + dj] * wrow[dj];
                }
            }
            // fire + store pool-group-contiguous: cell (row, cc=j+7h)
            // addr = oc*196 + ((row>>1)*7 + (cc>>1))*4 + (row&1)*2 + (cc&1)
            const int sbase = oc * 196 + (row >> 1) * 28 + (row & 1) * 2;
            #pragma unroll
            for (int j = 0; j < 7; j++) {
                float m  = m2r[j] + acc[j];
                float sp = (m >= TH) ? TH : 0.f;
                m2r[j]   = m - sp;
                int cc   = j + 7 * h;
                s2P[sbase + (cc >> 1) * 4 + (cc & 1)] = sp;
            }
        }
        __syncthreads();

        // D+E: fc with inline pooling (LDS.128 per pooled input), mem3 in regs
        {
            float part = 0.f;
            const float* wrow = wf + warp * 294;
            for (int k = lane; k < 294; k += 32) {
                float4 q = *reinterpret_cast<const float4*>(&s2P[k * 4]);
                part += (0.25f * (q.x + q.y + q.z + q.w)) * __ldg(&wrow[k]);
            }
            #pragma unroll
            for (int s = 16; s > 0; s >>= 1)
                part += __shfl_xor_sync(0xffffffffu, part, s);
            // row 'warp' (all lanes hold the full sum -> warp-uniform update)
            float m  = m3a + part + bfa;
            float sp = (m >= TH) ? TH : 0.f;
            m3a = m - sp;
            a3a += sp;
            if (lane == 0) {
                if (t == 3) out[(size_t)b * 10 + warp] = a3a * 0.25f;
                if (t == 7) out[(size_t)nb * 10 + (size_t)b * 10 + warp] = a3a * 0.125f;
            }
            if (warp < 3) {
                float part2 = 0.f;
                const float* wrow2 = wf + (7 + warp) * 294;
                for (int k = lane; k < 294; k += 32) {
                    float4 q = *reinterpret_cast<const float4*>(&s2P[k * 4]);
                    part2 += (0.25f * (q.x + q.y + q.z + q.w)) * __ldg(&wrow2[k]);
                }
                #pragma unroll
                for (int s = 16; s > 0; s >>= 1)
                    part2 += __shfl_xor_sync(0xffffffffu, part2, s);
                float n  = m3b + part2 + bfb;
                float sq = (n >= TH) ? TH : 0.f;
                m3b = n - sq;
                a3b += sq;
                if (lane == 0) {
                    if (t == 3) out[(size_t)b * 10 + 7 + warp] = a3b * 0.25f;
                    if (t == 7) out[(size_t)nb * 10 + (size_t)b * 10 + 7 + warp] = a3b * 0.125f;
                }
            }
        }

        // A(t+1): independent of D (p1h free since B(t) done) — same no-barrier region
        if (t < TSTEPS - 1) phaseA();
        __syncthreads();
    }
}

extern "C" void kernel_launch(void* const* d_in, const int* in_sizes, int n_in,
                              void* d_out, int out_size)
{
    const float* x  = (const float*)d_in[0];
    const float* w1 = (const float*)d_in[1];
    const float* b1 = (const float*)d_in[2];
    const float* w2 = (const float*)d_in[3];
    const float* b2 = (const float*)d_in[4];
    const float* wf = (const float*)d_in[5];
    const float* bf = (const float*)d_in[6];
    float* out = (float*)d_out;

    int nb = in_sizes[0] / 784;   // 4096
    snn_kernel<<<nb, NT>>>(x, w1, b1, w2, b2, wf, bf, out, nb);
}

// round 10
// speedup vs baseline: 1.2819x; 1.1252x over previous
#include <cuda_runtime.h>
#include <cuda_fp16.h>

// SpikeCNN fused: one block = one image, all 8 timesteps.
// R10: warp-specialized pipeline. Warps 0-5: conv2(B) + pool1(A). Warp 6: fc/mem3(D)
//      for the PREVIOUS timestep, overlapped with B via double-buffered s2P/p1h.
//      One barrier per timestep. Pooled p2 computed once per step into warp-6 regs.

#define TH 1.0f
#define TSTEPS 8
#define NT 224
#define XPITCH 33          // xpadT: col*33 + row (col-major)
#define C1CP 30            // c1s: c*840 + col*30 + row (col-major)
#define P1P 12             // p1h: [ic][rh(36)][k(12)] halves (k 0..10 used)
#define P1SZ (3 * 36 * P1P)

__global__ __launch_bounds__(NT, 4)
void snn_kernel(const float* __restrict__ x,
                const float* __restrict__ w1, const float* __restrict__ b1,
                const float* __restrict__ w2, const float* __restrict__ b2,
                const float* __restrict__ wf, const float* __restrict__ bf,
                float* __restrict__ out, int nb)
{
    __shared__ __align__(16) float  xpadT[32 * XPITCH];   // 1056 f32
    __shared__ __align__(16) float  c1s[3 * 28 * C1CP];   // 2520 f32 (col-major)
    __shared__ __align__(16) __half p1h[2][P1SZ];         // double-buffered
    __shared__ __align__(16) float  w2d[6 * 3 * 5 * 8];   // [oc][ic][di][8] padded
    __shared__ __align__(16) float  s2P[2][6 * 196];      // double-buffered [oc][grp][4]

    const int tid  = threadIdx.x;
    const int warp = tid >> 5;              // 0..6
    const int lane = tid & 31;
    const int b    = blockIdx.x;

    // ---- init ----
    for (int i = tid; i < 32 * XPITCH; i += NT) xpadT[i] = 0.f;
    for (int i = tid; i < 2 * P1SZ; i += NT)    p1h[0][i] = __float2half(0.f);
    for (int i = tid; i < 720; i += NT)         w2d[i]   = 0.f;
    __syncthreads();
    for (int i = tid; i < 450; i += NT) {
        int g = i / 5, dj = i - 5 * g;      // g = (oc*3+ic)*5+di
        w2d[g * 8 + dj] = w2[i];
    }
    const float* xb = x + (size_t)b * 784;
    for (int i = tid; i < 784; i += NT) {
        int r = i / 28, c = i % 28;
        xpadT[(c + 2) * XPITCH + (r + 2)] = xb[i];
    }
    __syncthreads();

    // ---- conv1 (once): warps 0..5 ----
    if (warp < 6 && lane < 28) {
        int c = warp % 3, colbase = (warp / 3) * 14, row = lane;
        float wr[25];
        #pragma unroll
        for (int k = 0; k < 25; k++) wr[k] = __ldg(&w1[c * 25 + k]);
        float bias = __ldg(&b1[c]);
        float acc[14];
        #pragma unroll
        for (int j = 0; j < 14; j++) acc[j] = bias;
        #pragma unroll
        for (int di = 0; di < 5; di++) {
            float v[18];
            #pragma unroll
            for (int k = 0; k < 18; k++)
                v[k] = xpadT[(colbase + k) * XPITCH + row + di];
            #pragma unroll
            for (int j = 0; j < 14; j++)
                #pragma unroll
                for (int dj = 0; dj < 5; dj++)
                    acc[j] += v[j + dj] * wr[di * 5 + dj];
        }
        #pragma unroll
        for (int j = 0; j < 14; j++)
            c1s[c * 840 + (colbase + j) * C1CP + row] = acc[j];
    }
    __syncthreads();   // c1s complete before phaseA reads it

    // ---- persistent register state ----
    float mr[12];                           // mem1: 3 tasks x 4 cells (all 7 warps)
    #pragma unroll
    for (int i = 0; i < 12; i++) mr[i] = 0.f;
    float m2r[7];                           // mem2: warps 0..5, oc = warp
    #pragma unroll
    for (int j = 0; j < 7; j++) m2r[j] = 0.f;
    const bool bact = (warp < 6 && lane < 28);
    const float b2r = bact ? __ldg(&b2[warp]) : 0.f;
    // mem3/acc3: warp-6 registers (warp-uniform across its lanes)
    float m3[10], a3[10];
    #pragma unroll
    for (int r = 0; r < 10; r++) { m3[r] = 0.f; a3[r] = 0.f; }

    const int  pi   = lane % 14;            // phase-A pooled row
    const int  dpj  = lane / 14;            // 0/1
    const bool aact = (lane < 28);

    // Phase A: mem1 += c1, fire, 2x2 pool -> p1h[pb]
    auto phaseA = [&](int pb) {
        if (aact) {
            __half* p1 = p1h[pb];
            #pragma unroll
            for (int i = 0; i < 3; i++) {
                int task = warp * 3 + i;                // 0..20 (warp 6 -> 18..20)
                int c    = task / 7;
                int pp   = task - 7 * c;
                int pj   = 2 * pp + dpj;
                int base = c * 840 + (2 * pj) * C1CP + 2 * pi;
                float2 ca = *reinterpret_cast<const float2*>(&c1s[base]);
                float2 cb = *reinterpret_cast<const float2*>(&c1s[base + C1CP]);
                float m0 = mr[i * 4 + 0] + ca.x;
                float m1 = mr[i * 4 + 1] + ca.y;
                float m2 = mr[i * 4 + 2] + cb.x;
                float m3v = mr[i * 4 + 3] + cb.y;
                float s0 = (m0 >= TH) ? TH : 0.f;
                float s1 = (m1 >= TH) ? TH : 0.f;
                float s2 = (m2 >= TH) ? TH : 0.f;
                float s3 = (m3v >= TH) ? TH : 0.f;
                mr[i * 4 + 0] = m0 - s0;
                mr[i * 4 + 1] = m1 - s1;
                mr[i * 4 + 2] = m2 - s2;
                mr[i * 4 + 3] = m3v - s3;
                __half val = __float2half_rn(0.25f * (s0 + s1 + s2 + s3));
                int cpad = pj + 2;                      // 2..15
                int rb   = c * 432 + (pi + 2) * 2 * P1P;
                if (cpad <= 10) p1[rb + cpad] = val;             // h=0 row
                if (cpad >= 7)  p1[rb + P1P + (cpad - 7)] = val; // h=1 row
            }
        }
    };

    // Phase D (warp 6): fc + mem3 fire for timestep td, reading s2P[td&1]
    auto phaseD = [&](int td) {
        const float* buf = s2P[td & 1];
        float pv[10];
        #pragma unroll
        for (int i = 0; i < 10; i++) {
            int k = lane + 32 * i;
            if (k < 294) {
                float4 q = *reinterpret_cast<const float4*>(&buf[k * 4]);
                pv[i] = 0.25f * (q.x + q.y + q.z + q.w);
            } else pv[i] = 0.f;
        }
        #pragma unroll
        for (int r = 0; r < 10; r++) {
            float part = 0.f;
            const float* wrow = wf + r * 294;
            #pragma unroll
            for (int i = 0; i < 10; i++) {
                int k = lane + 32 * i;
                if (k < 294) part += pv[i] * __ldg(&wrow[k]);
            }
            #pragma unroll
            for (int s = 16; s > 0; s >>= 1)
                part += __shfl_xor_sync(0xffffffffu, part, s);
            float m  = m3[r] + part + __ldg(&bf[r]);
            float sp = (m >= TH) ? TH : 0.f;
            m3[r] = m - sp;
            a3[r] += sp;
            if (lane == 0) {
                if (td == 3) out[(size_t)b * 10 + r] = a3[r] * 0.25f;
                if (td == 7) out[(size_t)nb * 10 + (size_t)b * 10 + r] = a3[r] * 0.125f;
            }
        }
    };

    phaseA(0);           // p1 for t=0
    __syncthreads();

    // ---- pipelined time loop: ONE barrier per timestep ----
    for (int t = 0; t < TSTEPS; t++) {
        if (warp < 6) {
            // B(t): conv2 + mem2 fire. reads p1h[t&1], writes s2P[t&1]
            if (lane < 28) {
                const __half* p1 = p1h[t & 1];
                const int oc  = warp;
                const int row = lane >> 1, h = lane & 1;
                float acc[7];
                #pragma unroll
                for (int j = 0; j < 7; j++) acc[j] = b2r;
                #pragma unroll
                for (int ic = 0; ic < 3; ic++) {
                    #pragma unroll
                    for (int di = 0; di < 5; di++) {
                        const __half2* src = reinterpret_cast<const __half2*>(
                            &p1[ic * 432 + (lane + 2 * di) * P1P]);
                        uint2 ra  = *reinterpret_cast<const uint2*>(src);
                        uint2 rb2 = *reinterpret_cast<const uint2*>(src + 2);
                        uint2 rc  = *reinterpret_cast<const uint2*>(src + 4);
                        float2 f0 = __half22float2(*reinterpret_cast<__half2*>(&ra.x));
                        float2 f1 = __half22float2(*reinterpret_cast<__half2*>(&ra.y));
                        float2 f2 = __half22float2(*reinterpret_cast<__half2*>(&rb2.x));
                        float2 f3 = __half22float2(*reinterpret_cast<__half2*>(&rb2.y));
                        float2 f4 = __half22float2(*reinterpret_cast<__half2*>(&rc.x));
                        float2 f5 = __half22float2(*reinterpret_cast<__half2*>(&rc.y));
                        float v[12] = {f0.x, f0.y, f1.x, f1.y, f2.x, f2.y,
                                       f3.x, f3.y, f4.x, f4.y, f5.x, f5.y};
                        const float* wp = &w2d[((oc * 3 + ic) * 5 + di) * 8];
                        float4 w4 = *reinterpret_cast<const float4*>(wp);
                        float  w5 = wp[4];
                        float wrow[5] = {w4.x, w4.y, w4.z, w4.w, w5};
                        #pragma unroll
                        for (int j = 0; j < 7; j++)
                            #pragma unroll
                            for (int dj = 0; dj < 5; dj++)
                                acc[j] += v[j + dj] * wrow[dj];
                    }
                }
                // fire + store pool-group-contiguous into s2P[t&1]
                float* sdst = s2P[t & 1];
                const int sbase = oc * 196 + (row >> 1) * 28 + (row & 1) * 2;
                #pragma unroll
                for (int j = 0; j < 7; j++) {
                    float m  = m2r[j] + acc[j];
                    float sp = (m >= TH) ? TH : 0.f;
                    m2r[j]   = m - sp;
                    int cc   = j + 7 * h;
                    sdst[sbase + (cc >> 1) * 4 + (cc & 1)] = sp;
                }
            }
            if (t < TSTEPS - 1) phaseA((t + 1) & 1);
        } else {
            // warp 6: D for previous timestep, then its A share
            if (t > 0) phaseD(t - 1);
            if (t < TSTEPS - 1) phaseA((t + 1) & 1);
        }
        __syncthreads();
    }
    // epilogue: D for the last timestep
    if (warp == 6) phaseD(TSTEPS - 1);
}

extern "C" void kernel_launch(void* const* d_in, const int* in_sizes, int n_in,
                              void* d_out, int out_size)
{
    const float* x  = (const float*)d_in[0];
    const float* w1 = (const float*)d_in[1];
    const float* b1 = (const float*)d_in[2];
    const float* w2 = (const float*)d_in[3];
    const float* b2 = (const float*)d_in[4];
    const float* wf = (const float*)d_in[5];
    const float* bf = (const float*)d_in[6];
    float* out = (float*)d_out;

    int nb = in_sizes[0] / 784;   // 4096
    snn_kernel<<<nb, NT>>>(x, w1, b1, w2, b2, wf, bf, out, nb);
}